// round 13
// baseline (speedup 1.0000x reference)
#include <cuda_runtime.h>
#include <cuda_fp16.h>

// ---- static problem shape -------------------------------------------------
#define BATCH   8
#define HH      32
#define WWID    32
#define CDIM    768
#define NHEADS  12
#define HD      64
#define SEQ     1024
#define BHEADS  96
#define N_QKV   2304

// ---- scratch (device globals; allocation is forbidden) ---------------------
__device__ __align__(256) __half g_Q  [(size_t)BHEADS * SEQ * HD];   // pre-scaled 1/8
__device__ __align__(256) __half g_K  [(size_t)BHEADS * SEQ * HD];
__device__ __align__(256) __half g_Vt [(size_t)BHEADS * HD * SEQ];   // [bh][d][s]
__device__ __align__(256) float  g_RH [(size_t)BHEADS * SEQ * HH];
__device__ __align__(256) float  g_RW [(size_t)BHEADS * SEQ * WWID];
__device__ __align__(256) __half g_ATT[(size_t)BATCH * SEQ * CDIM];
__device__ __align__(256) __half g_X  [(size_t)BATCH * SEQ * CDIM];
__device__ __align__(256) __half g_W1t[(size_t)N_QKV * CDIM];        // [n][k]
__device__ __align__(256) __half g_W2t[(size_t)CDIM * CDIM];         // [n][k]

// ---- helpers ---------------------------------------------------------------
__device__ __forceinline__ unsigned pack_half2(float lo, float hi) {
    unsigned r;
    asm("cvt.rn.f16x2.f32 %0, %1, %2;" : "=r"(r) : "f"(hi), "f"(lo));
    return r;
}
__device__ __forceinline__ void mma_f16(float c[4], const unsigned a[4],
                                        const unsigned b0, const unsigned b1) {
    asm volatile(
        "mma.sync.aligned.m16n8k16.row.col.f32.f16.f16.f32 "
        "{%0,%1,%2,%3},{%4,%5,%6,%7},{%8,%9},{%0,%1,%2,%3};"
        : "+f"(c[0]), "+f"(c[1]), "+f"(c[2]), "+f"(c[3])
        : "r"(a[0]), "r"(a[1]), "r"(a[2]), "r"(a[3]), "r"(b0), "r"(b1));
}
__device__ __forceinline__ void ldm_x4(unsigned& r0, unsigned& r1,
                                       unsigned& r2, unsigned& r3,
                                       unsigned addr) {
    asm volatile("ldmatrix.sync.aligned.m8n8.x4.shared.b16 {%0,%1,%2,%3}, [%4];"
                 : "=r"(r0), "=r"(r1), "=r"(r2), "=r"(r3) : "r"(addr));
}
__device__ __forceinline__ unsigned s2u(const void* p) {
    return (unsigned)__cvta_generic_to_shared(p);
}
#define CP16(dst, src) \
    asm volatile("cp.async.cg.shared.global [%0], [%1], 16;" \
                 :: "r"(dst), "l"(src))
#define CPCOMMIT() asm volatile("cp.async.commit_group;")
#define CPWAIT(n)  asm volatile("cp.async.wait_group %0;" :: "n"(n))

// ===========================================================================
// Pre-pass 1: fp32 -> fp16 elementwise (hidden).
// ===========================================================================
__global__ void __launch_bounds__(256) cvt_kernel(
    const float4* __restrict__ src, uint2* __restrict__ dst, int n4)
{
    const int i = blockIdx.x * 256 + threadIdx.x;
    if (i < n4) {
        float4 v = src[i];
        dst[i] = make_uint2(pack_half2(v.x, v.y), pack_half2(v.z, v.w));
    }
}

// ===========================================================================
// Pre-pass 2: transpose + convert weights.  Wt[n][k] = fp16(W[k][n]).
// ===========================================================================
__global__ void __launch_bounds__(256) transpose_cvt_kernel(
    const float* __restrict__ W, __half* __restrict__ Wt, int K, int N)
{
    __shared__ float tile[32][33];
    const int n0 = blockIdx.x * 32, k0 = blockIdx.y * 32;
    const int tx = threadIdx.x & 31, ty = threadIdx.x >> 5;
#pragma unroll
    for (int r = 0; r < 32; r += 8)
        tile[ty + r][tx] = W[(size_t)(k0 + ty + r) * N + n0 + tx];
    __syncthreads();
#pragma unroll
    for (int r = 0; r < 32; r += 8)
        Wt[(size_t)(n0 + ty + r) * K + k0 + tx] = __float2half(tile[tx][ty + r]);
}

// ===========================================================================
// fp16 GEMM:  out(8192 x N) = X @ W + bias, computed transposed
// (D = W^T @ X^T).  Block 128N x 128M, k-step 64, 2-stage cp.async,
// ldmatrix fragment loads.  Stage: Wsm[128][36] + Xsm[128][36] = 9216 words.
// ===========================================================================
template<bool QKV_SCATTER>
__global__ void __launch_bounds__(256, 2) gemm_f16_kernel(
    const __half* __restrict__ X, const __half* __restrict__ Wt,
    const float* __restrict__ bias, float* __restrict__ out)
{
    extern __shared__ unsigned smem[];   // 2 * 9216 words

    const int t = threadIdx.x;
    const int w = t >> 5, lane = t & 31, g = lane >> 2, t4 = lane & 3;
    const int warpN = (w & 3) * 32, warpM = (w >> 2) * 64;
    const int bn = blockIdx.x * 128, bm = blockIdx.y * 128;

    const int li = lane >> 3, lr = lane & 7;
    // ldmatrix per-lane word offsets (relative to tile base)
    const int aoff = (warpN + lr + ((li & 1) << 3)) * 36 + ((li >> 1) << 2);
    const int boff = (warpM + lr + ((li >> 1) << 3)) * 36 + ((li & 1) << 2);

    const int crow = t >> 1;            // 0..127
    const int chalf = (t & 1) * 16;     // word offset 0 or 16

    auto issue = [&](int i_, int s_) {
        unsigned* Wsm = smem + s_ * 9216;
        unsigned* Xsm = Wsm + 4608;
        const __half* srcW = Wt + (size_t)(bn + crow) * CDIM
                             + (i_ * 32 + chalf) * 2;
        const __half* srcX = X + (size_t)(bm + crow) * CDIM
                             + (i_ * 32 + chalf) * 2;
#pragma unroll
        for (int c = 0; c < 4; c++) {
            CP16(s2u(Wsm + crow * 36 + chalf + c * 4), srcW + c * 8);
            CP16(s2u(Xsm + crow * 36 + chalf + c * 4), srcX + c * 8);
        }
        CPCOMMIT();
    };

    float acc[2][8][4] = {};

    issue(0, 0);

    for (int i = 0; i < 12; i++) {
        const int s = i & 1;
        unsigned* Wsm = smem + s * 9216;
        unsigned* Xsm = Wsm + 4608;
        const unsigned wbase = s2u(Wsm), xbase = s2u(Xsm);

        CPWAIT(0);
        __syncthreads();
        if (i + 1 < 12) issue(i + 1, s ^ 1);

#pragma unroll
        for (int ks = 0; ks < 4; ks++) {
            const int kw = ks * 8;
            unsigned a[2][4];
            ldm_x4(a[0][0], a[0][1], a[0][2], a[0][3],
                   wbase + (aoff + kw) * 4);
            ldm_x4(a[1][0], a[1][1], a[1][2], a[1][3],
                   wbase + (aoff + 16 * 36 + kw) * 4);
#pragma unroll
            for (int np = 0; np < 4; np++) {
                unsigned b0, b1, b2, b3;
                ldm_x4(b0, b1, b2, b3,
                       xbase + (boff + np * 16 * 36 + kw) * 4);
                mma_f16(acc[0][2 * np],     a[0], b0, b1);
                mma_f16(acc[1][2 * np],     a[1], b0, b1);
                mma_f16(acc[0][2 * np + 1], a[0], b2, b3);
                mma_f16(acc[1][2 * np + 1], a[1], b2, b3);
            }
        }
    }

#pragma unroll
    for (int mt = 0; mt < 2; mt++) {
#pragma unroll
        for (int nt = 0; nt < 8; nt++) {
            const int ncol0 = bn + warpN + mt * 16 + g;
            const int mrow  = bm + warpM + nt * 8 + 2 * t4;
#pragma unroll
            for (int h8 = 0; h8 < 2; h8++) {
                const int ncol = ncol0 + h8 * 8;
                const float bs = __ldg(bias + ncol);
                const float v0 = acc[mt][nt][h8 * 2 + 0] + bs;
                const float v1 = acc[mt][nt][h8 * 2 + 1] + bs;
                if (QKV_SCATTER) {
                    const int which = ncol / CDIM;
                    const int rem   = ncol - which * CDIM;
                    const int h = rem >> 6, d = rem & 63;
                    const int b_ = mrow >> 10, s_ = mrow & 1023;
                    const int bh = b_ * NHEADS + h;
                    if (which == 2) {
                        __half* vp = g_Vt + ((size_t)bh * HD + d) * SEQ + s_;
                        vp[0] = __float2half(v0);
                        vp[1] = __float2half(v1);
                    } else {
                        __half* dst = (which == 0) ? g_Q : g_K;
                        const float sc = (which == 0) ? 0.125f : 1.0f;
                        const size_t base =
                            ((size_t)bh * SEQ + s_) * HD + d;
                        dst[base]      = __float2half(v0 * sc);
                        dst[base + HD] = __float2half(v1 * sc);
                    }
                } else {
                    out[(size_t)mrow * CDIM + ncol]       = v0;
                    out[(size_t)(mrow + 1) * CDIM + ncol] = v1;
                }
            }
        }
    }
}

// ===========================================================================
// relative-position bias (Q fp16, pre-scaled 1/8 -> output x8).
// ===========================================================================
__global__ void __launch_bounds__(256) rel_kernel(
    const float* __restrict__ rph, const float* __restrict__ rpw)
{
    __shared__ float Qs[32 * 65];
    __shared__ float Hs[32 * 65];
    __shared__ float Wt[63 * 65];

    const int bh = blockIdx.y;
    const int qh = blockIdx.x;
    const int t  = threadIdx.x;

    const __half* Qg = g_Q + ((size_t)bh * SEQ + qh * 32) * HD;
#pragma unroll
    for (int i = t; i < 2048; i += 256) {
        const int r = i >> 6, d = i & 63;
        Qs[r * 65 + d] = __half2float(Qg[i]);
        Hs[r * 65 + d] = __ldg(rph + (qh + r) * 64 + d);
    }
    for (int i = t; i < 4032; i += 256) {
        const int r = i >> 6, d = i & 63;
        Wt[r * 65 + d] = __ldg(rpw + i);
    }
    __syncthreads();

    const int w = t >> 5, lane = t & 31;
    const float* Qr = Qs + lane * 65;
    float acc[8] = {};

    if (w < 4) {
        const int baserow = 31 - w * 8;
#pragma unroll
        for (int d = 0; d < 64; d++) {
            const float qv = Qr[d];
#pragma unroll
            for (int j = 0; j < 8; j++)
                acc[j] = fmaf(qv, Hs[(baserow - j) * 65 + d], acc[j]);
        }
        float* out = g_RH + ((size_t)bh * SEQ + qh * 32 + lane) * HH + w * 8;
        *(float4*)out       = make_float4(acc[0]*8.f, acc[1]*8.f, acc[2]*8.f, acc[3]*8.f);
        *(float4*)(out + 4) = make_float4(acc[4]*8.f, acc[5]*8.f, acc[6]*8.f, acc[7]*8.f);
    } else {
        const int baserow = lane + 31 - (w - 4) * 8;
#pragma unroll
        for (int d = 0; d < 64; d++) {
            const float qv = Qr[d];
#pragma unroll
            for (int j = 0; j < 8; j++)
                acc[j] = fmaf(qv, Wt[(baserow - j) * 65 + d], acc[j]);
        }
        float* out = g_RW + ((size_t)bh * SEQ + qh * 32 + lane) * WWID
                     + (w - 4) * 8;
        *(float4*)out       = make_float4(acc[0]*8.f, acc[1]*8.f, acc[2]*8.f, acc[3]*8.f);
        *(float4*)(out + 4) = make_float4(acc[4]*8.f, acc[5]*8.f, acc[6]*8.f, acc[7]*8.f);
    }
}

// ===========================================================================
// fp16 flash attention.  Block = 64 queries (4 warps x 16), key tiles of 64.
// 2-stage cp.async K/V ring; ldmatrix for K and V fragments; softmaxed S
// packs directly into PV A-fragments.  Stage: Ks[64][36] + Vs[64][36].
// rw bias index = key & 31 = (nt&3)*8 + 2*t4  (the round-9..11 OOB fix).
// ===========================================================================
__global__ void __launch_bounds__(128, 3) flash_f16_kernel()
{
    extern __shared__ unsigned fsm[];   // 2 * 4608 words

    const int t = threadIdx.x, w = t >> 5, lane = t & 31;
    const int g = lane >> 2, t4 = lane & 3;
    const int bh = blockIdx.y;
    const int q0 = blockIdx.x * 64;
    const int qrow = w * 16;

    const __half* Kg  = g_K  + (size_t)bh * SEQ * HD;
    const __half* Vtg = g_Vt + (size_t)bh * HD * SEQ;

    const int li = lane >> 3, lr = lane & 7;
    const int qaoff = (qrow + lr + ((li & 1) << 3)) * 36 + ((li >> 1) << 2);
    const int nboff = (lr + ((li >> 1) << 3)) * 36 + ((li & 1) << 2);

    const int cr = t & 63;          // row
    const int cp_ = (t >> 6) * 16;  // word offset 0 or 16

    auto fissue = [&](int kt_, int s_) {
        unsigned* Kst = fsm + s_ * 4608;
        unsigned* Vst = Kst + 2304;
        const __half* srcK = Kg + (size_t)(kt_ * 64 + cr) * HD + cp_ * 2;
        const __half* srcV = Vtg + (size_t)cr * SEQ + kt_ * 64 + cp_ * 2;
#pragma unroll
        for (int c = 0; c < 4; c++) {
            CP16(s2u(Kst + cr * 36 + cp_ + c * 4), srcK + c * 8);
            CP16(s2u(Vst + cr * 36 + cp_ + c * 4), srcV + c * 8);
        }
        CPCOMMIT();
    };

    // ---- stage Q tile through stage-0 K area, pull fragments ---------------
    {
        const __half* Qg = g_Q + ((size_t)bh * SEQ + q0) * HD;
#pragma unroll
        for (int j = 0; j < 4; j++) {
            const int idx = t + 128 * j;
            const int row = idx >> 3, u4 = idx & 7;
            *(uint4*)&fsm[row * 36 + u4 * 4] =
                *(const uint4*)(Qg + (size_t)row * HD + u4 * 8);
        }
        __syncthreads();
    }
    unsigned qa[4][4];
    {
        const unsigned qbase = s2u(fsm);
#pragma unroll
        for (int c = 0; c < 4; c++)
            ldm_x4(qa[c][0], qa[c][1], qa[c][2], qa[c][3],
                   qbase + (qaoff + c * 8) * 4);
    }
    __syncthreads();   // all Q frags read before tile 0 overwrites stage 0

    // ---- rw bias (tile-invariant, 32-wide) into registers ------------------
    const float* RWg = g_RW + ((size_t)bh * SEQ + q0) * 32;
    float rwA[4][2], rwB[4][2];
#pragma unroll
    for (int nb = 0; nb < 4; nb++) {
        rwA[nb][0] = __ldg(RWg + (qrow + g) * 32 + nb * 8 + 2 * t4);
        rwA[nb][1] = __ldg(RWg + (qrow + g) * 32 + nb * 8 + 2 * t4 + 1);
        rwB[nb][0] = __ldg(RWg + (qrow + g + 8) * 32 + nb * 8 + 2 * t4);
        rwB[nb][1] = __ldg(RWg + (qrow + g + 8) * 32 + nb * 8 + 2 * t4 + 1);
    }
    const float* RHg = g_RH + ((size_t)bh * SEQ + q0) * 32;

    float o[8][4] = {};
    float l0 = 0.f, l1 = 0.f;

    fissue(0, 0);

    for (int kt = 0; kt < 16; kt++) {
        const int s = kt & 1;
        unsigned* Kst = fsm + s * 4608;
        unsigned* Vst = Kst + 2304;
        const unsigned kbase = s2u(Kst), vbase = s2u(Vst);

        CPWAIT(0);
        __syncthreads();
        if (kt + 1 < 16) fissue(kt + 1, s ^ 1);

        // ---- S = Q @ K^T ----------------------------------------------------
        float sreg[8][4] = {};
#pragma unroll
        for (int c = 0; c < 4; c++) {
            const int kw = c * 8;
#pragma unroll
            for (int np = 0; np < 4; np++) {
                unsigned b0, b1, b2, b3;
                ldm_x4(b0, b1, b2, b3,
                       kbase + (nboff + np * 16 * 36 + kw) * 4);
                mma_f16(sreg[2 * np],     qa[c], b0, b1);
                mma_f16(sreg[2 * np + 1], qa[c], b2, b3);
            }
        }

        // ---- softmax -> packed P fragments ----------------------------------
        const float rhA0 = __ldg(RHg + (qrow + g) * 32 + kt * 2);
        const float rhA1 = __ldg(RHg + (qrow + g) * 32 + kt * 2 + 1);
        const float rhB0 = __ldg(RHg + (qrow + g + 8) * 32 + kt * 2);
        const float rhB1 = __ldg(RHg + (qrow + g + 8) * 32 + kt * 2 + 1);
        unsigned pk[8][2];
#pragma unroll
        for (int nt = 0; nt < 8; nt++) {
            const float bA = (nt < 4) ? rhA0 : rhA1;
            const float bB = (nt < 4) ? rhB0 : rhB1;
            const int n4 = nt & 3;   // key&31 = (nt&3)*8 + 2*t4
            const float p00 = __expf(fminf(sreg[nt][0] + bA + rwA[n4][0], 60.f));
            const float p01 = __expf(fminf(sreg[nt][1] + bA + rwA[n4][1], 60.f));
            const float p10 = __expf(fminf(sreg[nt][2] + bB + rwB[n4][0], 60.f));
            const float p11 = __expf(fminf(sreg[nt][3] + bB + rwB[n4][1], 60.f));
            l0 += p00 + p01;
            l1 += p10 + p11;
            pk[nt][0] = pack_half2(p00, p01);
            pk[nt][1] = pack_half2(p10, p11);
        }

        // ---- O += P @ V -----------------------------------------------------
#pragma unroll
        for (int kv = 0; kv < 4; kv++) {
            unsigned ap[4];
            ap[0] = pk[2 * kv][0];
            ap[1] = pk[2 * kv][1];
            ap[2] = pk[2 * kv + 1][0];
            ap[3] = pk[2 * kv + 1][1];
            const int kw = kv * 8;
#pragma unroll
            for (int dp = 0; dp < 4; dp++) {
                unsigned b0, b1, b2, b3;
                ldm_x4(b0, b1, b2, b3,
                       vbase + (nboff + dp * 16 * 36 + kw) * 4);
                mma_f16(o[2 * dp],     ap, b0, b1);
                mma_f16(o[2 * dp + 1], ap, b2, b3);
            }
        }
    }

    // ---- finalize -----------------------------------------------------------
    l0 += __shfl_xor_sync(0xffffffffu, l0, 1);
    l0 += __shfl_xor_sync(0xffffffffu, l0, 2);
    l1 += __shfl_xor_sync(0xffffffffu, l1, 1);
    l1 += __shfl_xor_sync(0xffffffffu, l1, 2);
    const float inv0 = 1.f / l0;
    const float inv1 = 1.f / l1;

    const int b_ = bh / NHEADS, h = bh - b_ * NHEADS;
    const int rowA = q0 + qrow + g, rowB = rowA + 8;
    __half* OgA = g_ATT + ((size_t)b_ * SEQ + rowA) * CDIM + h * HD;
    __half* OgB = g_ATT + ((size_t)b_ * SEQ + rowB) * CDIM + h * HD;
#pragma unroll
    for (int db = 0; db < 8; db++) {
        const int c = db * 8 + 2 * t4;
        OgA[c]     = __float2half(o[db][0] * inv0);
        OgA[c + 1] = __float2half(o[db][1] * inv0);
        OgB[c]     = __float2half(o[db][2] * inv1);
        OgB[c + 1] = __float2half(o[db][3] * inv1);
    }
}

// ===========================================================================
// launch
// ===========================================================================
#define GEMM_SMEM  (2 * 9216 * 4)
#define FLASH_SMEM (2 * 4608 * 4)

extern "C" void kernel_launch(void* const* d_in, const int* in_sizes, int n_in,
                              void* d_out, int out_size)
{
    const float* hidden = (const float*)d_in[0];
    const float* qkv_w  = (const float*)d_in[1];
    const float* qkv_b  = (const float*)d_in[2];
    const float* proj_w = (const float*)d_in[3];
    const float* proj_b = (const float*)d_in[4];
    const float* rph    = (const float*)d_in[5];
    const float* rpw    = (const float*)d_in[6];
    float* out = (float*)d_out;

    static bool init = false;
    if (!init) {
        cudaFuncSetAttribute(gemm_f16_kernel<true>,
                             cudaFuncAttributeMaxDynamicSharedMemorySize,
                             GEMM_SMEM);
        cudaFuncSetAttribute(gemm_f16_kernel<false>,
                             cudaFuncAttributeMaxDynamicSharedMemorySize,
                             GEMM_SMEM);
        init = true;
    }

    __half *x_ptr = nullptr, *w1t_ptr = nullptr, *w2t_ptr = nullptr,
           *att_ptr = nullptr;
    cudaGetSymbolAddress((void**)&x_ptr,   g_X);
    cudaGetSymbolAddress((void**)&w1t_ptr, g_W1t);
    cudaGetSymbolAddress((void**)&w2t_ptr, g_W2t);
    cudaGetSymbolAddress((void**)&att_ptr, g_ATT);

    // pre-convert hidden; transpose+convert weights
    {
        const int nX = BATCH * SEQ * CDIM / 4;
        cvt_kernel<<<(nX + 255) / 256, 256>>>((const float4*)hidden,
                                              (uint2*)x_ptr, nX);
        transpose_cvt_kernel<<<dim3(N_QKV / 32, CDIM / 32), 256>>>(
            qkv_w, w1t_ptr, CDIM, N_QKV);
        transpose_cvt_kernel<<<dim3(CDIM / 32, CDIM / 32), 256>>>(
            proj_w, w2t_ptr, CDIM, CDIM);
    }

    gemm_f16_kernel<true>
        <<<dim3(N_QKV / 128, (BATCH * SEQ) / 128), 256, GEMM_SMEM>>>(
            x_ptr, w1t_ptr, qkv_b, nullptr);
    rel_kernel<<<dim3(HH, BHEADS), 256>>>(rph, rpw);
    flash_f16_kernel<<<dim3(SEQ / 64, BHEADS), 128, FLASH_SMEM>>>();
    gemm_f16_kernel<false>
        <<<dim3(CDIM / 128, (BATCH * SEQ) / 128), 256, GEMM_SMEM>>>(
            att_ptr, w2t_ptr, proj_b, out);
}

// round 14
// speedup vs baseline: 1.1933x; 1.1933x over previous
#include <cuda_runtime.h>
#include <cuda_fp16.h>

// ---- static problem shape -------------------------------------------------
#define BATCH   8
#define HH      32
#define WWID    32
#define CDIM    768
#define NHEADS  12
#define HD      64
#define SEQ     1024
#define BHEADS  96
#define N_QKV   2304

// ---- scratch (device globals; allocation is forbidden) ---------------------
__device__ __align__(256) __half g_Q  [(size_t)BHEADS * SEQ * HD];   // pre-scaled 1/8
__device__ __align__(256) __half g_K  [(size_t)BHEADS * SEQ * HD];
__device__ __align__(256) __half g_Vt [(size_t)BHEADS * HD * SEQ];   // [bh][d][s]
__device__ __align__(256) float  g_RH [(size_t)BHEADS * SEQ * HH];
__device__ __align__(256) float  g_RW [(size_t)BHEADS * SEQ * WWID];
__device__ __align__(256) __half g_ATT[(size_t)BATCH * SEQ * CDIM];
__device__ __align__(256) __half g_X  [(size_t)BATCH * SEQ * CDIM];
__device__ __align__(256) __half g_W1t[(size_t)N_QKV * CDIM];        // [n][k]
__device__ __align__(256) __half g_W2t[(size_t)CDIM * CDIM];         // [n][k]

// ---- helpers ---------------------------------------------------------------
__device__ __forceinline__ unsigned pack_half2(float lo, float hi) {
    unsigned r;
    asm("cvt.rn.f16x2.f32 %0, %1, %2;" : "=r"(r) : "f"(hi), "f"(lo));
    return r;
}
__device__ __forceinline__ void mma_f16(float c[4], const unsigned a[4],
                                        const unsigned b0, const unsigned b1) {
    asm volatile(
        "mma.sync.aligned.m16n8k16.row.col.f32.f16.f16.f32 "
        "{%0,%1,%2,%3},{%4,%5,%6,%7},{%8,%9},{%0,%1,%2,%3};"
        : "+f"(c[0]), "+f"(c[1]), "+f"(c[2]), "+f"(c[3])
        : "r"(a[0]), "r"(a[1]), "r"(a[2]), "r"(a[3]), "r"(b0), "r"(b1));
}

// ===========================================================================
// Pre-pass 1: fp32 -> fp16 elementwise (hidden).
// ===========================================================================
__global__ void __launch_bounds__(256) cvt_kernel(
    const float4* __restrict__ src, uint2* __restrict__ dst, int n4)
{
    const int i = blockIdx.x * 256 + threadIdx.x;
    if (i < n4) {
        float4 v = src[i];
        dst[i] = make_uint2(pack_half2(v.x, v.y), pack_half2(v.z, v.w));
    }
}

// ===========================================================================
// Pre-pass 2: transpose + convert weights.  Wt[n][k] = fp16(W[k][n]).
// ===========================================================================
__global__ void __launch_bounds__(256) transpose_cvt_kernel(
    const float* __restrict__ W, __half* __restrict__ Wt, int K, int N)
{
    __shared__ float tile[32][33];
    const int n0 = blockIdx.x * 32, k0 = blockIdx.y * 32;
    const int tx = threadIdx.x & 31, ty = threadIdx.x >> 5;
#pragma unroll
    for (int r = 0; r < 32; r += 8)
        tile[ty + r][tx] = W[(size_t)(k0 + ty + r) * N + n0 + tx];
    __syncthreads();
#pragma unroll
    for (int r = 0; r < 32; r += 8)
        Wt[(size_t)(n0 + ty + r) * K + k0 + tx] = __float2half(tile[tx][ty + r]);
}

// ===========================================================================
// fp16 GEMM (round-12 proven): out = X @ W + bias, computed transposed.
// Block 128N x 128M, k-step 64, synchronous copies, per-k8 LDS fragments.
// ===========================================================================
template<bool QKV_SCATTER>
__global__ void __launch_bounds__(256, 2) gemm_f16_kernel(
    const __half* __restrict__ X, const __half* __restrict__ Wt,
    const float* __restrict__ bias, float* __restrict__ out)
{
    __shared__ unsigned Wsm[128 * 36];
    __shared__ unsigned Xsm[128 * 36];

    const int t = threadIdx.x;
    const int w = t >> 5, lane = t & 31, g = lane >> 2, t4 = lane & 3;
    const int warpN = (w & 3) * 32, warpM = (w >> 2) * 64;
    const int bn = blockIdx.x * 128, bm = blockIdx.y * 128;

    float acc[2][8][4] = {};

    for (int i = 0; i < 12; i++) {
        uint4 wreg[4], xreg[4];
#pragma unroll
        for (int j = 0; j < 4; j++) {
            const int idx = t + 256 * j;
            const int row = idx >> 3, u4 = idx & 7;
            wreg[j] = *(const uint4*)(Wt + (size_t)(bn + row) * CDIM
                                      + i * 64 + u4 * 8);
            xreg[j] = *(const uint4*)(X + (size_t)(bm + row) * CDIM
                                      + i * 64 + u4 * 8);
        }
        __syncthreads();
#pragma unroll
        for (int j = 0; j < 4; j++) {
            const int idx = t + 256 * j;
            const int row = idx >> 3, u4 = idx & 7;
            *(uint4*)&Wsm[row * 36 + u4 * 4] = wreg[j];
            *(uint4*)&Xsm[row * 36 + u4 * 4] = xreg[j];
        }
        __syncthreads();

#pragma unroll
        for (int ks = 0; ks < 4; ks++) {
            const int kw = ks * 8;
            unsigned a[2][4];
#pragma unroll
            for (int mt = 0; mt < 2; mt++) {
                const int nr = warpN + mt * 16 + g;
                a[mt][0] = Wsm[nr * 36 + kw + t4];
                a[mt][1] = Wsm[(nr + 8) * 36 + kw + t4];
                a[mt][2] = Wsm[nr * 36 + kw + t4 + 4];
                a[mt][3] = Wsm[(nr + 8) * 36 + kw + t4 + 4];
            }
#pragma unroll
            for (int nt = 0; nt < 8; nt++) {
                const int mr = (warpM + nt * 8 + g) * 36 + kw;
                const unsigned b0 = Xsm[mr + t4];
                const unsigned b1 = Xsm[mr + t4 + 4];
                mma_f16(acc[0][nt], a[0], b0, b1);
                mma_f16(acc[1][nt], a[1], b0, b1);
            }
        }
    }

#pragma unroll
    for (int mt = 0; mt < 2; mt++) {
#pragma unroll
        for (int nt = 0; nt < 8; nt++) {
            const int ncol0 = bn + warpN + mt * 16 + g;
            const int mrow  = bm + warpM + nt * 8 + 2 * t4;
#pragma unroll
            for (int h8 = 0; h8 < 2; h8++) {
                const int ncol = ncol0 + h8 * 8;
                const float bs = __ldg(bias + ncol);
                const float v0 = acc[mt][nt][h8 * 2 + 0] + bs;
                const float v1 = acc[mt][nt][h8 * 2 + 1] + bs;
                if (QKV_SCATTER) {
                    const int which = ncol / CDIM;
                    const int rem   = ncol - which * CDIM;
                    const int h = rem >> 6, d = rem & 63;
                    const int b_ = mrow >> 10, s_ = mrow & 1023;
                    const int bh = b_ * NHEADS + h;
                    if (which == 2) {
                        __half* vp = g_Vt + ((size_t)bh * HD + d) * SEQ + s_;
                        vp[0] = __float2half(v0);
                        vp[1] = __float2half(v1);
                    } else {
                        __half* dst = (which == 0) ? g_Q : g_K;
                        const float sc = (which == 0) ? 0.125f : 1.0f;
                        const size_t base =
                            ((size_t)bh * SEQ + s_) * HD + d;
                        dst[base]      = __float2half(v0 * sc);
                        dst[base + HD] = __float2half(v1 * sc);
                    }
                } else {
                    out[(size_t)mrow * CDIM + ncol]       = v0;
                    out[(size_t)(mrow + 1) * CDIM + ncol] = v1;
                }
            }
        }
    }
}

// ===========================================================================
// relative-position bias (Q fp16, pre-scaled 1/8 -> output x8).
// ===========================================================================
__global__ void __launch_bounds__(256) rel_kernel(
    const float* __restrict__ rph, const float* __restrict__ rpw)
{
    __shared__ float Qs[32 * 65];
    __shared__ float Hs[32 * 65];
    __shared__ float Wt[63 * 65];

    const int bh = blockIdx.y;
    const int qh = blockIdx.x;
    const int t  = threadIdx.x;

    const __half* Qg = g_Q + ((size_t)bh * SEQ + qh * 32) * HD;
#pragma unroll
    for (int i = t; i < 2048; i += 256) {
        const int r = i >> 6, d = i & 63;
        Qs[r * 65 + d] = __half2float(Qg[i]);
        Hs[r * 65 + d] = __ldg(rph + (qh + r) * 64 + d);
    }
    for (int i = t; i < 4032; i += 256) {
        const int r = i >> 6, d = i & 63;
        Wt[r * 65 + d] = __ldg(rpw + i);
    }
    __syncthreads();

    const int w = t >> 5, lane = t & 31;
    const float* Qr = Qs + lane * 65;
    float acc[8] = {};

    if (w < 4) {
        const int baserow = 31 - w * 8;
#pragma unroll
        for (int d = 0; d < 64; d++) {
            const float qv = Qr[d];
#pragma unroll
            for (int j = 0; j < 8; j++)
                acc[j] = fmaf(qv, Hs[(baserow - j) * 65 + d], acc[j]);
        }
        float* out = g_RH + ((size_t)bh * SEQ + qh * 32 + lane) * HH + w * 8;
        *(float4*)out       = make_float4(acc[0]*8.f, acc[1]*8.f, acc[2]*8.f, acc[3]*8.f);
        *(float4*)(out + 4) = make_float4(acc[4]*8.f, acc[5]*8.f, acc[6]*8.f, acc[7]*8.f);
    } else {
        const int baserow = lane + 31 - (w - 4) * 8;
#pragma unroll
        for (int d = 0; d < 64; d++) {
            const float qv = Qr[d];
#pragma unroll
            for (int j = 0; j < 8; j++)
                acc[j] = fmaf(qv, Wt[(baserow - j) * 65 + d], acc[j]);
        }
        float* out = g_RW + ((size_t)bh * SEQ + qh * 32 + lane) * WWID
                     + (w - 4) * 8;
        *(float4*)out       = make_float4(acc[0]*8.f, acc[1]*8.f, acc[2]*8.f, acc[3]*8.f);
        *(float4*)(out + 4) = make_float4(acc[4]*8.f, acc[5]*8.f, acc[6]*8.f, acc[7]*8.f);
    }
}

// ===========================================================================
// fp16 flash attention, 128 queries per block (8 warps x 16 rows), 64-key
// tiles.  Per-warp compute identical to round 12; K/V copy + barriers are
// amortized over 2x the queries.  Smem = one combined 4608-word buffer
// (Ks rows 0-63, Vs rows 64-127); Q (128 rows) stages through all of it.
// rw bias index = key & 31 = (nt&3)*8 + 2*t4.
// ===========================================================================
__global__ void __launch_bounds__(256, 2) flash_f16_kernel()
{
    __shared__ unsigned sm[4608];        // Ks = sm[0..2303], Vs = sm[2304..]
    unsigned* Ks = sm;
    unsigned* Vs = sm + 2304;

    const int t = threadIdx.x, w = t >> 5, lane = t & 31;
    const int g = lane >> 2, t4 = lane & 3;
    const int bh = blockIdx.y;
    const int q0 = blockIdx.x * 128;
    const int qrow = w * 16;

    const __half* Kg  = g_K  + (size_t)bh * SEQ * HD;
    const __half* Vtg = g_Vt + (size_t)bh * HD * SEQ;

    // ---- stage Q tile (128 rows) across the whole buffer, pull fragments ---
    {
        const __half* Qg = g_Q + ((size_t)bh * SEQ + q0) * HD;
#pragma unroll
        for (int j = 0; j < 4; j++) {
            const int idx = t + 256 * j;
            const int row = idx >> 3, u4 = idx & 7;
            *(uint4*)&sm[row * 36 + u4 * 4] =
                *(const uint4*)(Qg + (size_t)row * HD + u4 * 8);
        }
        __syncthreads();
    }
    unsigned qa[4][4];
#pragma unroll
    for (int c = 0; c < 4; c++) {
        const int kw = c * 8;
        qa[c][0] = sm[(qrow + g) * 36 + kw + t4];
        qa[c][1] = sm[(qrow + g + 8) * 36 + kw + t4];
        qa[c][2] = sm[(qrow + g) * 36 + kw + t4 + 4];
        qa[c][3] = sm[(qrow + g + 8) * 36 + kw + t4 + 4];
    }
    __syncthreads();   // all Q frags read before tile 0 overwrites the buffer

    // ---- rw bias (tile-invariant, 32-wide) into registers ------------------
    const float* RWg = g_RW + ((size_t)bh * SEQ + q0) * 32;
    float rwA[4][2], rwB[4][2];
#pragma unroll
    for (int nb = 0; nb < 4; nb++) {
        rwA[nb][0] = __ldg(RWg + (qrow + g) * 32 + nb * 8 + 2 * t4);
        rwA[nb][1] = __ldg(RWg + (qrow + g) * 32 + nb * 8 + 2 * t4 + 1);
        rwB[nb][0] = __ldg(RWg + (qrow + g + 8) * 32 + nb * 8 + 2 * t4);
        rwB[nb][1] = __ldg(RWg + (qrow + g + 8) * 32 + nb * 8 + 2 * t4 + 1);
    }
    const float* RHg = g_RH + ((size_t)bh * SEQ + q0) * 32;

    float o[8][4] = {};
    float l0 = 0.f, l1 = 0.f;

    for (int kt = 0; kt < 16; kt++) {
        uint4 kreg[2], vreg[2];
#pragma unroll
        for (int j = 0; j < 2; j++) {
            const int idx = t + 256 * j;
            const int row = idx >> 3, u4 = idx & 7;
            kreg[j] = *(const uint4*)(Kg + (size_t)(kt * 64 + row) * HD
                                      + u4 * 8);
            vreg[j] = *(const uint4*)(Vtg + (size_t)row * SEQ + kt * 64
                                      + u4 * 8);
        }
        __syncthreads();
#pragma unroll
        for (int j = 0; j < 2; j++) {
            const int idx = t + 256 * j;
            const int row = idx >> 3, u4 = idx & 7;
            *(uint4*)&Ks[row * 36 + u4 * 4] = kreg[j];
            *(uint4*)&Vs[row * 36 + u4 * 4] = vreg[j];
        }
        __syncthreads();

        // ---- S = Q @ K^T ----------------------------------------------------
        float sreg[8][4] = {};
#pragma unroll
        for (int c = 0; c < 4; c++) {
            const int kw = c * 8;
#pragma unroll
            for (int nt = 0; nt < 8; nt++) {
                const int kr = (nt * 8 + g) * 36 + kw;
                const unsigned b0 = Ks[kr + t4];
                const unsigned b1 = Ks[kr + t4 + 4];
                mma_f16(sreg[nt], qa[c], b0, b1);
            }
        }

        // ---- softmax -> packed P fragments ----------------------------------
        const float rhA0 = __ldg(RHg + (qrow + g) * 32 + kt * 2);
        const float rhA1 = __ldg(RHg + (qrow + g) * 32 + kt * 2 + 1);
        const float rhB0 = __ldg(RHg + (qrow + g + 8) * 32 + kt * 2);
        const float rhB1 = __ldg(RHg + (qrow + g + 8) * 32 + kt * 2 + 1);
        unsigned pk[8][2];
#pragma unroll
        for (int nt = 0; nt < 8; nt++) {
            const float bA = (nt < 4) ? rhA0 : rhA1;
            const float bB = (nt < 4) ? rhB0 : rhB1;
            const int n4 = nt & 3;   // key&31 = (nt&3)*8 + 2*t4
            const float p00 = __expf(fminf(sreg[nt][0] + bA + rwA[n4][0], 60.f));
            const float p01 = __expf(fminf(sreg[nt][1] + bA + rwA[n4][1], 60.f));
            const float p10 = __expf(fminf(sreg[nt][2] + bB + rwB[n4][0], 60.f));
            const float p11 = __expf(fminf(sreg[nt][3] + bB + rwB[n4][1], 60.f));
            l0 += p00 + p01;
            l1 += p10 + p11;
            pk[nt][0] = pack_half2(p00, p01);
            pk[nt][1] = pack_half2(p10, p11);
        }

        // ---- O += P @ V -----------------------------------------------------
#pragma unroll
        for (int kv = 0; kv < 4; kv++) {
            unsigned ap[4];
            ap[0] = pk[2 * kv][0];
            ap[1] = pk[2 * kv][1];
            ap[2] = pk[2 * kv + 1][0];
            ap[3] = pk[2 * kv + 1][1];
            const int kw = kv * 8;
#pragma unroll
            for (int db = 0; db < 8; db++) {
                const int vr = (db * 8 + g) * 36 + kw;
                const unsigned b0 = Vs[vr + t4];
                const unsigned b1 = Vs[vr + t4 + 4];
                mma_f16(o[db], ap, b0, b1);
            }
        }
    }

    // ---- finalize -----------------------------------------------------------
    l0 += __shfl_xor_sync(0xffffffffu, l0, 1);
    l0 += __shfl_xor_sync(0xffffffffu, l0, 2);
    l1 += __shfl_xor_sync(0xffffffffu, l1, 1);
    l1 += __shfl_xor_sync(0xffffffffu, l1, 2);
    const float inv0 = 1.f / l0;
    const float inv1 = 1.f / l1;

    const int b_ = bh / NHEADS, h = bh - b_ * NHEADS;
    const int rowA = q0 + qrow + g, rowB = rowA + 8;
    __half* OgA = g_ATT + ((size_t)b_ * SEQ + rowA) * CDIM + h * HD;
    __half* OgB = g_ATT + ((size_t)b_ * SEQ + rowB) * CDIM + h * HD;
#pragma unroll
    for (int db = 0; db < 8; db++) {
        const int c = db * 8 + 2 * t4;
        OgA[c]     = __float2half(o[db][0] * inv0);
        OgA[c + 1] = __float2half(o[db][1] * inv0);
        OgB[c]     = __float2half(o[db][2] * inv1);
        OgB[c + 1] = __float2half(o[db][3] * inv1);
    }
}

// ===========================================================================
// launch
// ===========================================================================
extern "C" void kernel_launch(void* const* d_in, const int* in_sizes, int n_in,
                              void* d_out, int out_size)
{
    const float* hidden = (const float*)d_in[0];
    const float* qkv_w  = (const float*)d_in[1];
    const float* qkv_b  = (const float*)d_in[2];
    const float* proj_w = (const float*)d_in[3];
    const float* proj_b = (const float*)d_in[4];
    const float* rph    = (const float*)d_in[5];
    const float* rpw    = (const float*)d_in[6];
    float* out = (float*)d_out;

    __half *x_ptr = nullptr, *w1t_ptr = nullptr, *w2t_ptr = nullptr,
           *att_ptr = nullptr;
    cudaGetSymbolAddress((void**)&x_ptr,   g_X);
    cudaGetSymbolAddress((void**)&w1t_ptr, g_W1t);
    cudaGetSymbolAddress((void**)&w2t_ptr, g_W2t);
    cudaGetSymbolAddress((void**)&att_ptr, g_ATT);

    // pre-convert hidden; transpose+convert weights
    {
        const int nX = BATCH * SEQ * CDIM / 4;
        cvt_kernel<<<(nX + 255) / 256, 256>>>((const float4*)hidden,
                                              (uint2*)x_ptr, nX);
        transpose_cvt_kernel<<<dim3(N_QKV / 32, CDIM / 32), 256>>>(
            qkv_w, w1t_ptr, CDIM, N_QKV);
        transpose_cvt_kernel<<<dim3(CDIM / 32, CDIM / 32), 256>>>(
            proj_w, w2t_ptr, CDIM, CDIM);
    }

    gemm_f16_kernel<true>
        <<<dim3(N_QKV / 128, (BATCH * SEQ) / 128), 256>>>(
            x_ptr, w1t_ptr, qkv_b, nullptr);
    rel_kernel<<<dim3(HH, BHEADS), 256>>>(rph, rpw);
    flash_f16_kernel<<<dim3(SEQ / 128, BHEADS), 256>>>();
    gemm_f16_kernel<false>
        <<<dim3(CDIM / 128, (BATCH * SEQ) / 128), 256>>>(
            att_ptr, w2t_ptr, proj_b, out);
}